// round 3
// baseline (speedup 1.0000x reference)
#include <cuda_runtime.h>

#define BATCH 32
#define TSTEPS 1024
#define COLS 2048
#define SPLIT 4
#define THREADS 512   /* = COLS / SPLIT, 1 column per thread */
#define WARPS (THREADS / 32)

// Relay slots: one 64-bit word per (block, t). hi32 = ready flag, lo32 = float bits.
__device__ unsigned long long g_relay[BATCH * SPLIT * TSTEPS];

__device__ __forceinline__ unsigned long long ld_acq(const unsigned long long* p) {
    unsigned long long v;
    asm volatile("ld.acquire.gpu.global.b64 %0, [%1];" : "=l"(v) : "l"(p) : "memory");
    return v;
}
__device__ __forceinline__ void st_rel(unsigned long long* p, unsigned long long v) {
    asm volatile("st.release.gpu.global.b64 [%0], %1;" :: "l"(p), "l"(v) : "memory");
}

__global__ __launch_bounds__(THREADS, 1)
void softscan_kernel(const float* __restrict__ x, float* __restrict__ out) {
    const int s    = blockIdx.x;          // column-block within batch
    const int b    = blockIdx.y;          // batch
    const int tid  = threadIdx.x;
    const int lane = tid & 31;
    const int warp = tid >> 5;
    const int col  = s * THREADS + tid;

    __shared__ float sh[2][WARPS];        // double-buffered warp-seam values

    const float* xp = x   + (size_t)b * TSTEPS * COLS + col;
    float*       op = out + (size_t)b * TSTEPS * COLS + col;

    unsigned long long*       my_slot = g_relay + (size_t)(b * SPLIT + s) * TSTEPS;
    const unsigned long long* src     = g_relay + (size_t)(b * SPLIT + s - 1) * TSTEPS;
    const bool producer = (tid == THREADS - 1) && (s != SPLIT - 1);

    // ---- t = 0: carry = x[b,0,col] ----
    float c = __ldcs(xp);
    __stcs(op, c);
    if (lane == 31) sh[0][warp] = c;
    if (producer) st_rel(my_slot, (1ull << 32) | (unsigned long long)__float_as_uint(c));
    float xnext = __ldcs(xp + COLS);      // prefetch t=1
    __syncthreads();

    #pragma unroll 1
    for (int t = 1; t < TSTEPS; ++t) {
        float xv = xnext;
        if (t + 1 < TSTEPS) xnext = __ldcs(xp + (size_t)(t + 1) * COLS);  // prefetch next step

        // neighbor carry (col-1) from previous step
        float left = __shfl_up_sync(0xffffffffu, c, 1);
        if (lane == 0) {
            if (warp > 0) {
                left = sh[(t - 1) & 1][warp - 1];
            } else if (s != 0) {
                unsigned long long v;
                do { v = ld_acq(src + (t - 1)); } while (!(v >> 32));
                left = __uint_as_float((unsigned int)v);
            }
        }

        float nc;
        if (col == 0) {
            // vals[:,0] = a[:,0]  ->  new = x + carry
            nc = xv + c;
        } else {
            float d = c - left;                       // a - b
            float e = __expf(-d);                     // MUFU.EX2 path
            float p = __fdividef(1.0f, 1.0f + e);     // sigmoid via MUFU.RCP
            nc = xv + fmaf(p, d, left);               // x + b + p*(a-b)
        }
        c = nc;

        __stcs(op + (size_t)t * COLS, c);
        if (lane == 31) sh[t & 1][warp] = c;
        if (producer) st_rel(my_slot + t, (1ull << 32) | (unsigned long long)__float_as_uint(c));
        __syncthreads();
    }
}

extern "C" void kernel_launch(void* const* d_in, const int* in_sizes, int n_in,
                              void* d_out, int out_size) {
    const float* x = (const float*)d_in[0];
    float* out = (float*)d_out;

    // Reset relay flags every launch (captured as a memset node -> replay-safe).
    void* relay_ptr = nullptr;
    cudaGetSymbolAddress(&relay_ptr, g_relay);
    cudaMemsetAsync(relay_ptr, 0, sizeof(unsigned long long) * BATCH * SPLIT * TSTEPS, 0);

    dim3 grid(SPLIT, BATCH);   // 128 blocks <= 148 SMs: single wave, relay is deadlock-free
    softscan_kernel<<<grid, THREADS>>>(x, out);
}

// round 4
// speedup vs baseline: 2.7595x; 2.7595x over previous
#include <cuda_runtime.h>

#define BATCH   32
#define TSTEPS  1024
#define COLS    2048
#define SPLIT   4
#define THREADS 128            /* threads per block */
#define V       4              /* columns per thread (float4) */
#define WARPS   (THREADS / 32)
#define ROW4    (COLS / 4)     /* row stride in float4 = 512 */
#define DPF     8              /* x prefetch depth in time steps */
#define KREL    8              /* relay prefetch depth in time steps */

/* One 64-bit word per (batch,block,t): hi32 = ready flag, lo32 = float bits.
   Flag and value live in the same word -> relaxed 64-bit atomics suffice. */
__device__ unsigned long long g_relay[BATCH * SPLIT * TSTEPS];

__device__ __forceinline__ unsigned long long ld_rlx(const unsigned long long* p) {
    unsigned long long v;
    asm volatile("ld.relaxed.gpu.global.b64 %0, [%1];" : "=l"(v) : "l"(p) : "memory");
    return v;
}
__device__ __forceinline__ void st_rlx(unsigned long long* p, unsigned long long v) {
    asm volatile("st.relaxed.gpu.global.b64 [%0], %1;" :: "l"(p), "l"(v) : "memory");
}

__device__ __forceinline__ float smix(float a, float b) {
    float d = a - b;                      /* a - b            */
    float e = __expf(-d);                 /* MUFU.EX2 path    */
    float p = __fdividef(1.0f, 1.0f + e); /* MUFU.RCP path    */
    return fmaf(p, d, b);                 /* b + p*(a-b)      */
}

__global__ __launch_bounds__(THREADS, 1)
void softscan_kernel(const float* __restrict__ x, float* __restrict__ out) {
    const int s    = blockIdx.x;           /* column-block within batch */
    const int b    = blockIdx.y;           /* batch                     */
    const int tid  = threadIdx.x;
    const int lane = tid & 31;
    const int warp = tid >> 5;
    const int col0 = (s * THREADS + tid) * V;

    __shared__ float sh[2][WARPS];         /* double-buffered warp-seam values */

    const float4* xp = (const float4*)(x   + (size_t)b * TSTEPS * COLS + col0);
    float4*       op = (float4*)      (out + (size_t)b * TSTEPS * COLS + col0);

    unsigned long long*       my_slot = g_relay + (size_t)(b * SPLIT + s)     * TSTEPS;
    const unsigned long long* src     = g_relay + (size_t)(b * SPLIT + s - 1) * TSTEPS;
    const bool producer = (tid == THREADS - 1) && (s != SPLIT - 1);
    const bool consumer = (tid == 0) && (s != 0);
    const bool firstcol = (tid == 0) && (s == 0);   /* owns global column 0 */

    /* ---- t = 0: carry = x[b,0,:] ---- */
    float4 c = __ldcs(xp);
    __stcs(op, c);
    if (lane == 31) sh[0][warp] = c.w;
    if (producer) st_rlx(my_slot, (1ull << 32) | (unsigned long long)__float_as_uint(c.w));

    /* x prefetch ring: rows 1..DPF */
    float4 buf[DPF];
    #pragma unroll
    for (int k = 0; k < DPF; ++k)
        buf[k] = __ldcs(xp + (size_t)(k + 1) * ROW4);

    /* relay prefetch queue: slots 0..KREL-1 (for steps 1..KREL) */
    unsigned long long pend[KREL];
    if (consumer) {
        #pragma unroll
        for (int k = 0; k < KREL; ++k) pend[k] = ld_rlx(src + k);
    }
    __syncthreads();

    #pragma unroll 8
    for (int t = 1; t < TSTEPS; ++t) {
        /* x row for this step: prefetched DPF steps ago */
        float4 xv = buf[(t - 1) % DPF];
        if (t + DPF < TSTEPS)
            buf[(t - 1) % DPF] = __ldcs(xp + (size_t)(t + DPF) * ROW4);

        /* neighbor carry (col0-1) from previous step */
        float left = __shfl_up_sync(0xffffffffu, c.w, 1);
        if (lane == 0) {
            if (warp > 0) {
                left = sh[(t - 1) & 1][warp - 1];
            } else if (consumer) {
                unsigned long long v = pend[(t - 1) % KREL];
                if (!(v >> 32)) {                     /* warm-up / skew fallback */
                    do { v = ld_rlx(src + (t - 1)); } while (!(v >> 32));
                }
                left = __uint_as_float((unsigned)v);
                if (t - 1 + KREL < TSTEPS - 1)        /* refill K ahead */
                    pend[(t - 1) % KREL] = ld_rlx(src + (t - 1 + KREL));
            }
        }

        /* all 4 mixes read OLD carries -> fully parallel */
        float4 nc;
        nc.x = firstcol ? (xv.x + c.x) : (xv.x + smix(c.x, left));
        nc.y = xv.y + smix(c.y, c.x);
        nc.z = xv.z + smix(c.z, c.y);
        nc.w = xv.w + smix(c.w, c.z);
        c = nc;

        __stcs(op + (size_t)t * ROW4, c);
        if (lane == 31) sh[t & 1][warp] = c.w;
        if (producer) st_rlx(my_slot + t, (1ull << 32) | (unsigned long long)__float_as_uint(c.w));
        __syncthreads();
    }
}

extern "C" void kernel_launch(void* const* d_in, const int* in_sizes, int n_in,
                              void* d_out, int out_size) {
    const float* x = (const float*)d_in[0];
    float* out = (float*)d_out;

    /* Reset relay flags every launch (captured memset node -> replay-safe). */
    void* relay_ptr = nullptr;
    cudaGetSymbolAddress(&relay_ptr, g_relay);
    cudaMemsetAsync(relay_ptr, 0, sizeof(unsigned long long) * BATCH * SPLIT * TSTEPS, 0);

    dim3 grid(SPLIT, BATCH);   /* 128 blocks <= 148 SMs: single wave, relay deadlock-free */
    softscan_kernel<<<grid, THREADS>>>(x, out);
}